// round 13
// baseline (speedup 1.0000x reference)
#include <cuda_runtime.h>
#include <cuda_fp16.h>
#include <cstdint>

#define NB 256   // batch
#define ND 16    // manifold dim
#define NH 128   // hidden

__device__ __forceinline__ __half2 tanh2h(__half2 x) {
    uint32_t xi, yi;
    xi = *reinterpret_cast<uint32_t*>(&x);
    asm("tanh.approx.f16x2 %0, %1;" : "=r"(yi) : "r"(xi));
    __half2 y = *reinterpret_cast<__half2*>(&yi);
    return y;
}
__device__ __forceinline__ __half2 u2h2(uint32_t u) {
    return *reinterpret_cast<__half2*>(&u);
}

struct WPack { __half2 w0, w1, w2, b; };   // 16 bytes

// ============================================================================
// K_ALL: one block per batch element b. 512 threads = (hi = t>>8, o = t&255).
//   P1: metric hidden (t<128) || christoffel weight conversion (t in [128,192))
//   P2: metric GEMM, h split 2x64 -> symmetrize + eps -> met
//   P3: pmr[8] (PB+M1, own i-half, registers) + m2s[16][o] (own j-half)
//   P4 Stage A: fp16x2 christoffel MLP; thread covers its (j,k) for 8 i's
//   P5 Stage B: fp16 ricci hidden sums over all j for 8 i's -> 2-way reduce
//   P6: output GEMM (h split 2x128) + bias -> symmetrize -> out
// ============================================================================
__global__ __launch_bounds__(512) void k_all(
    const float* __restrict__ points,
    const float* __restrict__ mW1, const float* __restrict__ mb1,
    const float* __restrict__ mW2, const float* __restrict__ mb2,
    const float* __restrict__ cW1, const float* __restrict__ cb1,
    const float* __restrict__ cW2, const float* __restrict__ cb2,
    const float* __restrict__ rW1, const float* __restrict__ rb1,
    const float* __restrict__ rW2, const float* __restrict__ rb2,
    float* __restrict__ out)
{
    int b  = blockIdx.x;
    int t  = threadIdx.x;   // 0..511
    int o  = t & 255;
    int hi = t >> 8;        // 0 or 1

    __shared__ float pts[ND];
    __shared__ float mh[NH];
    __shared__ float met[256];
    __shared__ float buf[256];            // mraw, later raw
    __shared__ float red[2][256];         // phase partials (reused 3x)
    __shared__ float Ss[256];
    __shared__ __align__(16) WPack   sW[NH / 2];
    __shared__ __align__(4)  __half2 sV[NH / 2];
    __shared__ float m2s[ND][256];
    __shared__ __align__(16) __half  chs[ND][256];

    // ---- P0: points ----
    if (t < ND) pts[t] = points[b * ND + t];
    __syncthreads();

    // ---- P1: metric hidden || weight conversion ----
    if (t < NH) {
        float a = mb1[t];
        #pragma unroll
        for (int p = 0; p < ND; p++) a = fmaf(pts[p], mW1[p * NH + t], a);
        mh[t] = fmaxf(a, 0.0f);
    } else if (t < NH + 64) {
        int q = t - NH;
        WPack w;
        w.w0 = __floats2half2_rn(cW1[2 * q],          cW1[2 * q + 1]);
        w.w1 = __floats2half2_rn(cW1[NH + 2 * q],     cW1[NH + 2 * q + 1]);
        w.w2 = __floats2half2_rn(cW1[2 * NH + 2 * q], cW1[2 * NH + 2 * q + 1]);
        w.b  = __floats2half2_rn(cb1[2 * q],          cb1[2 * q + 1]);
        sW[q] = w;
        sV[q] = __floats2half2_rn(cW2[2 * q], cW2[2 * q + 1]);
    }
    __syncthreads();

    // ---- P2: metric GEMM (h in [hi*64, hi*64+64), 2 interleaved chains) ----
    {
        int h0 = hi * 64;
        float a0 = 0.f, a1 = 0.f;
        #pragma unroll 8
        for (int h = 0; h < 32; h++) {
            a0 = fmaf(mh[h0 + h],      mW2[(h0 + h) * 256 + o],      a0);
            a1 = fmaf(mh[h0 + 32 + h], mW2[(h0 + 32 + h) * 256 + o], a1);
        }
        red[hi][o] = a0 + a1;
    }
    __syncthreads();
    if (t < 256) buf[t] = mb2[t] + red[0][t] + red[1][t];
    __syncthreads();
    if (t < 256) {
        int i = t >> 4, j = t & 15;
        met[t] = 0.5f * (buf[i * 16 + j] + buf[j * 16 + i])
               + (i == j ? 1e-6f : 0.0f);
    }
    __syncthreads();

    // ---- P3: pmr[8] (own i-half) + m2s (own j-half). Covered by P4's sync. ----
    float pmr[8];
    {
        float rwA[ND];
        #pragma unroll
        for (int p = 0; p < ND; p++) rwA[p] = rW1[(16 + p) * 256 + o];
        float pb = rb1[o];
        #pragma unroll
        for (int p = 0; p < ND; p++) pb = fmaf(pts[p], rW1[p * 256 + o], pb);
        #pragma unroll
        for (int ii = 0; ii < 8; ii++) {
            int i = hi * 8 + ii;
            float a = 0.0f;
            #pragma unroll
            for (int p = 0; p < ND; p++) a = fmaf(met[i * 16 + p], rwA[p], a);
            pmr[ii] = pb + a;
        }
        float rwB[ND];
        #pragma unroll
        for (int p = 0; p < ND; p++) rwB[p] = rW1[(32 + p) * 256 + o];
        #pragma unroll
        for (int jj = 0; jj < 8; jj++) {
            int j = hi * 8 + jj;
            float a = 0.0f;
            #pragma unroll
            for (int p = 0; p < ND; p++) a = fmaf(met[j * 16 + p], rwB[p], a);
            m2s[j][o] = a;
        }
    }

    // ---- P4 Stage A: christoffel for (i = hi*8 .. hi*8+8, j=o>>4, k=o&15) ----
    {
        int j = o >> 4, k = o & 15;
        __half2 mjk2 = __float2half2_rn(met[j * 16 + k]);
        __half2 mij2[8], mki2[8];
        #pragma unroll
        for (int ii = 0; ii < 8; ii++) {
            int i = hi * 8 + ii;
            mij2[ii] = __float2half2_rn(met[i * 16 + j]);
            mki2[ii] = __float2half2_rn(met[i * 16 + k]);  // metric symmetric
        }
        const __half2 z2 = __float2half2_rn(0.0f);
        float c0 = cb2[0];
        float facc[8];
        #pragma unroll
        for (int ii = 0; ii < 8; ii++) facc[ii] = c0;

        #pragma unroll
        for (int blk = 0; blk < 8; blk++) {
            __half2 acc[8];
            #pragma unroll
            for (int ii = 0; ii < 8; ii++) acc[ii] = z2;
            #pragma unroll
            for (int r = 0; r < 8; r++) {
                int q = blk * 8 + r;
                WPack w = sW[q];
                __half2 v = sV[q];
                #pragma unroll
                for (int ii = 0; ii < 8; ii++) {
                    __half2 x = __hfma2(mij2[ii], w.w0, w.b);
                    x = __hfma2(mjk2, w.w1, x);
                    x = __hfma2(mki2[ii], w.w2, x);
                    acc[ii] = __hfma2(v, tanh2h(x), acc[ii]);
                }
            }
            #pragma unroll
            for (int ii = 0; ii < 8; ii++) {
                float2 f = __half22float2(acc[ii]);
                facc[ii] += f.x + f.y;
            }
        }
        #pragma unroll
        for (int ii = 0; ii < 8; ii++)
            chs[hi * 8 + ii][o] = __float2half(facc[ii]);
    }
    __syncthreads();   // orders chs AND m2s for Stage B

    // ---- P5 Stage B: ricci hidden sums, i in own half, all 16 j ----
    {
        const float* rW1c = rW1 + 48 * 256;
        __half2 rwh[8];
        #pragma unroll
        for (int q = 0; q < 8; q++)
            rwh[q] = __floats2half2_rn(rW1c[(2 * q) * 256 + o],
                                       rW1c[(2 * q + 1) * 256 + o]);
        float s[8];
        #pragma unroll
        for (int ii = 0; ii < 8; ii++) s[ii] = 0.0f;
        const __half2 z2 = __float2half2_rn(0.0f);

        #pragma unroll 2
        for (int j = 0; j < ND; j++) {
            float m2 = m2s[j][o];
            #pragma unroll
            for (int ii = 0; ii < 8; ii++) {
                const uint4* cp = (const uint4*)&chs[hi * 8 + ii][j * 16];
                uint4 u0 = cp[0];
                uint4 u1 = cp[1];
                __half2 acc = z2;
                acc = __hfma2(u2h2(u0.x), rwh[0], acc);
                acc = __hfma2(u2h2(u0.y), rwh[1], acc);
                acc = __hfma2(u2h2(u0.z), rwh[2], acc);
                acc = __hfma2(u2h2(u0.w), rwh[3], acc);
                acc = __hfma2(u2h2(u1.x), rwh[4], acc);
                acc = __hfma2(u2h2(u1.y), rwh[5], acc);
                acc = __hfma2(u2h2(u1.z), rwh[6], acc);
                acc = __hfma2(u2h2(u1.w), rwh[7], acc);
                float2 f = __half22float2(acc);
                float a = pmr[ii] + m2 + f.x + f.y;
                s[ii] += fmaxf(a, 0.0f);
            }
        }
        float ssum = ((s[0] + s[1]) + (s[2] + s[3]))
                   + ((s[4] + s[5]) + (s[6] + s[7]));
        red[hi][o] = ssum;
    }
    __syncthreads();
    if (t < 256) Ss[t] = (red[0][t] + red[1][t]) * (1.0f / 256.0f);
    __syncthreads();

    // ---- P6: output GEMM (h in [hi*128, hi*128+128), 2 interleaved chains) ----
    {
        int h0 = hi * 128;
        float a0 = 0.f, a1 = 0.f;
        #pragma unroll 8
        for (int h = 0; h < 64; h++) {
            a0 = fmaf(Ss[h0 + h],      rW2[(h0 + h) * 256 + o],      a0);
            a1 = fmaf(Ss[h0 + 64 + h], rW2[(h0 + 64 + h) * 256 + o], a1);
        }
        red[hi][o] = a0 + a1;
    }
    __syncthreads();
    if (t < 256) buf[t] = rb2[t] + red[0][t] + red[1][t];
    __syncthreads();
    if (t < 256) {
        int i = t >> 4, j = t & 15;
        out[b * 256 + t] = 0.5f * (buf[i * 16 + j] + buf[j * 16 + i]);
    }
}

// ============================================================================
extern "C" void kernel_launch(void* const* d_in, const int* in_sizes, int n_in,
                              void* d_out, int out_size)
{
    const float* points = (const float*)d_in[0];
    const float* mW1    = (const float*)d_in[1];
    const float* mb1    = (const float*)d_in[2];
    const float* mW2    = (const float*)d_in[3];
    const float* mb2    = (const float*)d_in[4];
    const float* cW1    = (const float*)d_in[5];
    const float* cb1    = (const float*)d_in[6];
    const float* cW2    = (const float*)d_in[7];
    const float* cb2    = (const float*)d_in[8];
    const float* rW1    = (const float*)d_in[9];
    const float* rb1    = (const float*)d_in[10];
    const float* rW2    = (const float*)d_in[11];
    const float* rb2    = (const float*)d_in[12];
    float* out = (float*)d_out;

    k_all<<<NB, 512>>>(points, mW1, mb1, mW2, mb2,
                       cW1, cb1, cW2, cb2, rW1, rb1, rW2, rb2, out);
}